// round 2
// baseline (speedup 1.0000x reference)
#include <cuda_runtime.h>
#include <stdint.h>
#include <math_constants.h>

// Problem constants
#define B_   2
#define S_   2048
#define D_   1024
#define H_   16
#define DH_  64
#define MTOT (B_ * S_)   // 4096
#define MASK_N (B_ * S_ * S_)   // 8388608

// Scratch (device globals — allocation-free per harness rules)
__device__ float   g_q[MTOT * D_];
__device__ float   g_k[MTOT * D_];
__device__ float   g_v[MTOT * D_];
__device__ float   g_ctx[MTOT * D_];
__device__ uint8_t g_mask[MASK_N];
__device__ int     g_mask_flags;   // bit0: not-int32 evidence, bit1: not-float32 evidence

// ---------------------------------------------------------------------------
// Mask dtype detection: read first 4096 int32 words of the raw mask buffer.
//   all in {0,1}            -> int32
//   all in {0, 0x3F800000}  -> float32
//   otherwise               -> uint8 (1-byte bool)
// Single block; thread 0 writes the flag word (deterministic, no reset race).
// ---------------------------------------------------------------------------
__global__ __launch_bounds__(256) void detect_mask_kernel(const uint32_t* __restrict__ raw)
{
    __shared__ int sflags[256];
    int f = 0;
    const int tid = threadIdx.x;
    #pragma unroll
    for (int i = 0; i < 16; i++) {
        const uint32_t w = raw[tid * 16 + i];
        if (w != 0u && w != 1u)          f |= 1;   // not int32 0/1
        if (w != 0u && w != 0x3F800000u) f |= 2;   // not float32 0/1
    }
    sflags[tid] = f;
    __syncthreads();
    for (int s = 128; s > 0; s >>= 1) {
        if (tid < s) sflags[tid] |= sflags[tid + s];
        __syncthreads();
    }
    if (tid == 0) g_mask_flags = sflags[0];
}

// Normalize mask of whatever dtype into canonical uint8 (0 / 1).
__global__ __launch_bounds__(256) void convert_mask_kernel(const void* __restrict__ raw)
{
    const int flags = g_mask_flags;
    const size_t i0 = ((size_t)blockIdx.x * 256 + threadIdx.x) * 4;
    if (i0 >= MASK_N) return;
    uchar4 o;
    if ((flags & 1) == 0) {              // int32
        const int4 v = *reinterpret_cast<const int4*>((const int*)raw + i0);
        o = make_uchar4(v.x != 0, v.y != 0, v.z != 0, v.w != 0);
    } else if ((flags & 2) == 0) {       // float32
        const float4 v = *reinterpret_cast<const float4*>((const float*)raw + i0);
        o = make_uchar4(v.x != 0.f, v.y != 0.f, v.z != 0.f, v.w != 0.f);
    } else {                             // uint8 bool
        o = *reinterpret_cast<const uchar4*>((const uint8_t*)raw + i0);
        o = make_uchar4(o.x != 0, o.y != 0, o.z != 0, o.w != 0);
    }
    *reinterpret_cast<uchar4*>(g_mask + i0) = o;
}

// ---------------------------------------------------------------------------
// GEMM: out = (op(A) @ W^T + bias) * scale
//   A: [M=4096, K=1024]; W: [N=1024, K=1024] row-major; bias: [N]
//   amode 0: A plain row-major.  amode 1: A gathered from [B,H,S,DH] layout.
//   omode 0: out plain [M,N].    omode 1: out scattered to [B,H,S,DH].
// 64x64 tile, 256 threads, 4x4 per thread, K-step 16.
// ---------------------------------------------------------------------------
__global__ __launch_bounds__(256) void gemm_kernel(
    const float* __restrict__ A, const float* __restrict__ W,
    const float* __restrict__ bias, float* __restrict__ out,
    int amode, int omode, float scale)
{
    __shared__ float As[16][68];
    __shared__ float Ws[16][68];

    const int K = D_;
    const int tid  = threadIdx.x;
    const int row0 = blockIdx.y * 64;
    const int col0 = blockIdx.x * 64;

    const int lr  = tid >> 2;        // 0..63 (tile row for loads)
    const int lc4 = (tid & 3) * 4;   // 0,4,8,12 (k offset for loads)
    const int ty  = tid >> 4;        // 0..15
    const int tx  = tid & 15;        // 0..15

    float acc[4][4];
    #pragma unroll
    for (int i = 0; i < 4; i++)
        #pragma unroll
        for (int j = 0; j < 4; j++) acc[i][j] = 0.f;

    for (int k0 = 0; k0 < K; k0 += 16) {
        // load A tile (64 rows x 16 k), store transposed As[k][row]
        float4 av;
        {
            const int arow = row0 + lr;
            const int kk   = k0 + lc4;
            if (amode == 0) {
                av = *reinterpret_cast<const float4*>(A + (size_t)arow * K + kk);
            } else {
                const int b = arow >> 11, s = arow & (S_ - 1);
                const int h = kk >> 6,  dh = kk & 63;
                av = *reinterpret_cast<const float4*>(
                    A + ((((size_t)b * H_ + h) * S_ + s) << 6) + dh);
            }
        }
        As[lc4 + 0][lr] = av.x; As[lc4 + 1][lr] = av.y;
        As[lc4 + 2][lr] = av.z; As[lc4 + 3][lr] = av.w;

        // load W tile (rows = output features col0..col0+63)
        {
            const float4 wv = *reinterpret_cast<const float4*>(
                W + (size_t)(col0 + lr) * K + k0 + lc4);
            Ws[lc4 + 0][lr] = wv.x; Ws[lc4 + 1][lr] = wv.y;
            Ws[lc4 + 2][lr] = wv.z; Ws[lc4 + 3][lr] = wv.w;
        }
        __syncthreads();

        #pragma unroll
        for (int kk = 0; kk < 16; kk++) {
            const float4 a4 = *reinterpret_cast<const float4*>(&As[kk][ty * 4]);
            const float4 w4 = *reinterpret_cast<const float4*>(&Ws[kk][tx * 4]);
            const float a[4] = {a4.x, a4.y, a4.z, a4.w};
            const float w[4] = {w4.x, w4.y, w4.z, w4.w};
            #pragma unroll
            for (int i = 0; i < 4; i++)
                #pragma unroll
                for (int j = 0; j < 4; j++)
                    acc[i][j] = fmaf(a[i], w[j], acc[i][j]);
        }
        __syncthreads();
    }

    // epilogue
    const float4 bv = *reinterpret_cast<const float4*>(bias + col0 + tx * 4);
    #pragma unroll
    for (int i = 0; i < 4; i++) {
        const int m = row0 + ty * 4 + i;
        float4 o;
        o.x = (acc[i][0] + bv.x) * scale;
        o.y = (acc[i][1] + bv.y) * scale;
        o.z = (acc[i][2] + bv.z) * scale;
        o.w = (acc[i][3] + bv.w) * scale;
        if (omode == 0) {
            *reinterpret_cast<float4*>(out + (size_t)m * D_ + col0 + tx * 4) = o;
        } else {
            const int n = col0 + tx * 4;
            const int b = m >> 11, s = m & (S_ - 1);
            const int h = n >> 6,  dh = n & 63;
            *reinterpret_cast<float4*>(
                out + ((((size_t)b * H_ + h) * S_ + s) << 6) + dh) = o;
        }
    }
}

// ---------------------------------------------------------------------------
// Flash attention over head layout. One block = (b, h, 64-query tile).
// 256 threads: thread t handles query row r = t/4, 16 key/d-columns (t%4)*16..+15.
// Online softmax over 32 K-tiles of 64 keys.
// ---------------------------------------------------------------------------
#define FLD 68   // padded row stride in floats

__global__ __launch_bounds__(256) void flash_kernel()
{
    extern __shared__ float sm[];
    float* Qs = sm;                   // 64 * FLD
    float* Ks = Qs + 64 * FLD;
    float* Vs = Ks + 64 * FLD;
    float* Ps = Vs + 64 * FLD;

    const int tid = threadIdx.x;
    const int q0  = blockIdx.x * 64;
    const int h   = blockIdx.y;
    const int b   = blockIdx.z;
    const size_t head_base = ((size_t)b * H_ + h) * S_ * DH_;

    // load Q tile (64 x 64)
    #pragma unroll
    for (int i = 0; i < 4; i++) {
        const int f = tid + i * 256;         // float4 index, 1024 total
        const int r = f >> 4, c4 = (f & 15) << 2;
        *reinterpret_cast<float4*>(Qs + r * FLD + c4) =
            *reinterpret_cast<const float4*>(g_q + head_base + (size_t)(q0 + r) * DH_ + c4);
    }

    const int r  = tid >> 2;   // query row 0..63
    const int cq = tid & 3;    // key/dim quad 0..3

    float m_i = -CUDART_INF_F;
    float l_i = 0.f;
    float4 o4[4];
    #pragma unroll
    for (int j = 0; j < 4; j++) o4[j] = make_float4(0.f, 0.f, 0.f, 0.f);

    const uint8_t* mrow = g_mask + ((size_t)b * S_ + (q0 + r)) * S_ + cq * 16;

    __syncthreads();

    for (int kt = 0; kt < S_ / 64; kt++) {
        // load K,V tiles
        #pragma unroll
        for (int i = 0; i < 4; i++) {
            const int f = tid + i * 256;
            const int rr = f >> 4, c4 = (f & 15) << 2;
            const size_t gsrc = head_base + (size_t)(kt * 64 + rr) * DH_ + c4;
            *reinterpret_cast<float4*>(Ks + rr * FLD + c4) =
                *reinterpret_cast<const float4*>(g_k + gsrc);
            *reinterpret_cast<float4*>(Vs + rr * FLD + c4) =
                *reinterpret_cast<const float4*>(g_v + gsrc);
        }
        __syncthreads();

        // scores: sc[c] = q_row . k_{cq*16+c}
        float sc[16];
        #pragma unroll
        for (int c = 0; c < 16; c++) sc[c] = 0.f;
        #pragma unroll
        for (int kk = 0; kk < 16; kk++) {
            const float4 q4 = *reinterpret_cast<const float4*>(Qs + r * FLD + kk * 4);
            #pragma unroll
            for (int c = 0; c < 16; c++) {
                const float4 k4 = *reinterpret_cast<const float4*>(
                    Ks + (cq * 16 + c) * FLD + kk * 4);
                sc[c] = fmaf(q4.x, k4.x, sc[c]);
                sc[c] = fmaf(q4.y, k4.y, sc[c]);
                sc[c] = fmaf(q4.z, k4.z, sc[c]);
                sc[c] = fmaf(q4.w, k4.w, sc[c]);
            }
        }

        // mask (canonical uint8, 1 byte/elem): nonzero -> -1e18
        {
            const uint4 mv = *reinterpret_cast<const uint4*>(mrow + (size_t)kt * 64);
            const unsigned mb[4] = {mv.x, mv.y, mv.z, mv.w};
            #pragma unroll
            for (int c = 0; c < 16; c++) {
                if ((mb[c >> 2] >> ((c & 3) * 8)) & 0xffu) sc[c] = -1e18f;
            }
        }

        // online softmax (per-row; quad of 4 threads holds the row)
        float tmax = sc[0];
        #pragma unroll
        for (int c = 1; c < 16; c++) tmax = fmaxf(tmax, sc[c]);
        tmax = fmaxf(tmax, __shfl_xor_sync(0xffffffffu, tmax, 1));
        tmax = fmaxf(tmax, __shfl_xor_sync(0xffffffffu, tmax, 2));

        const float m_new = fmaxf(m_i, tmax);
        const float alpha = __expf(m_i - m_new);

        float lsum = 0.f;
        #pragma unroll
        for (int c = 0; c < 16; c++) {
            sc[c] = __expf(sc[c] - m_new);
            lsum += sc[c];
        }
        lsum += __shfl_xor_sync(0xffffffffu, lsum, 1);
        lsum += __shfl_xor_sync(0xffffffffu, lsum, 2);

        l_i = l_i * alpha + lsum;
        m_i = m_new;
        #pragma unroll
        for (int j = 0; j < 4; j++) {
            o4[j].x *= alpha; o4[j].y *= alpha; o4[j].z *= alpha; o4[j].w *= alpha;
        }

        // publish P row chunk
        #pragma unroll
        for (int j = 0; j < 4; j++) {
            *reinterpret_cast<float4*>(Ps + r * FLD + cq * 16 + j * 4) =
                make_float4(sc[j * 4 + 0], sc[j * 4 + 1], sc[j * 4 + 2], sc[j * 4 + 3]);
        }
        __syncthreads();

        // O += P @ V  (thread: 16 d-columns cq*16..+15)
        #pragma unroll 8
        for (int c = 0; c < 64; c++) {
            const float p = Ps[r * FLD + c];
            #pragma unroll
            for (int j = 0; j < 4; j++) {
                const float4 v4 = *reinterpret_cast<const float4*>(
                    Vs + c * FLD + cq * 16 + j * 4);
                o4[j].x = fmaf(p, v4.x, o4[j].x);
                o4[j].y = fmaf(p, v4.y, o4[j].y);
                o4[j].z = fmaf(p, v4.z, o4[j].z);
                o4[j].w = fmaf(p, v4.w, o4[j].w);
            }
        }
        __syncthreads();   // protect Ks/Vs/Ps before next tile
    }

    // finalize: ctx[b,h,q0+r, cq*16..] = o / l
    const float inv = 1.f / l_i;
    const size_t obase = head_base + (size_t)(q0 + r) * DH_ + cq * 16;
    #pragma unroll
    for (int j = 0; j < 4; j++) {
        float4 v = o4[j];
        v.x *= inv; v.y *= inv; v.z *= inv; v.w *= inv;
        *reinterpret_cast<float4*>(g_ctx + obase + j * 4) = v;
    }
}

// ---------------------------------------------------------------------------
extern "C" void kernel_launch(void* const* d_in, const int* in_sizes, int n_in,
                              void* d_out, int out_size)
{
    const float* key   = (const float*)d_in[0];
    const float* value = (const float*)d_in[1];
    const float* query = (const float*)d_in[2];
    const void*  mask  = d_in[3];
    const float* Wq = (const float*)d_in[4];
    const float* bq = (const float*)d_in[5];
    const float* Wk = (const float*)d_in[6];
    const float* bk = (const float*)d_in[7];
    const float* Wv = (const float*)d_in[8];
    const float* bv = (const float*)d_in[9];
    const float* Wo = (const float*)d_in[10];
    const float* bo = (const float*)d_in[11];
    float* out = (float*)d_out;

    void *pq, *pk, *pv, *pctx;
    cudaGetSymbolAddress(&pq,   g_q);
    cudaGetSymbolAddress(&pk,   g_k);
    cudaGetSymbolAddress(&pv,   g_v);
    cudaGetSymbolAddress(&pctx, g_ctx);

    // mask normalization (dtype-agnostic)
    detect_mask_kernel<<<1, 256>>>((const uint32_t*)mask);
    convert_mask_kernel<<<(MASK_N / 4 + 255) / 256, 256>>>(mask);

    const dim3 gb(D_ / 64, MTOT / 64);   // (16, 64)

    // QKV projections (Q pre-scaled by 1/sqrt(DH) = 0.125)
    gemm_kernel<<<gb, 256>>>(query, Wq, bq, (float*)pq, 0, 1, 0.125f);
    gemm_kernel<<<gb, 256>>>(key,   Wk, bk, (float*)pk, 0, 1, 1.f);
    gemm_kernel<<<gb, 256>>>(value, Wv, bv, (float*)pv, 0, 1, 1.f);

    // attention
    const size_t smem = (size_t)4 * 64 * FLD * sizeof(float);   // 69632 B
    cudaFuncSetAttribute(flash_kernel,
                         cudaFuncAttributeMaxDynamicSharedMemorySize, (int)smem);
    flash_kernel<<<dim3(S_ / 64, H_, B_), 256, smem>>>();

    // output projection
    gemm_kernel<<<gb, 256>>>((const float*)pctx, Wo, bo, out, 1, 0, 1.f);
}

// round 3
// speedup vs baseline: 2.1110x; 2.1110x over previous
#include <cuda_runtime.h>
#include <stdint.h>
#include <math_constants.h>

// Problem constants
#define B_   2
#define S_   2048
#define D_   1024
#define H_   16
#define DH_  64
#define MTOT (B_ * S_)          // 4096
#define MASK_N (B_ * S_ * S_)   // 8388608

// Scratch (device globals — allocation-free per harness rules)
__device__ float   g_q[MTOT * D_];    // transposed head layout [B,H,DH,S]
__device__ float   g_k[MTOT * D_];    // transposed head layout [B,H,DH,S]
__device__ float   g_v[MTOT * D_];    // natural head layout [B,H,S,DH]
__device__ float   g_ctx[MTOT * D_];  // natural head layout [B,H,S,DH]
__device__ uint8_t g_mask[MASK_N];
__device__ int     g_mask_flags;

// ---------------------------------------------------------------------------
// packed f32x2 helpers (FFMA2 — only reachable via PTX fma.rn.f32x2)
// ---------------------------------------------------------------------------
__device__ __forceinline__ void ffma2(uint64_t& d, uint64_t a, uint64_t b) {
    asm("fma.rn.f32x2 %0, %1, %2, %0;" : "+l"(d) : "l"(a), "l"(b));
}
__device__ __forceinline__ void fmul2(uint64_t& d, uint64_t a) {
    asm("mul.rn.f32x2 %0, %0, %1;" : "+l"(d) : "l"(a));
}
__device__ __forceinline__ uint64_t dup2(float x) {
    uint64_t r; asm("mov.b64 %0, {%1, %1};" : "=l"(r) : "f"(x)); return r;
}
__device__ __forceinline__ float2 unpack2(uint64_t v) {
    float2 r; asm("mov.b64 {%0, %1}, %2;" : "=f"(r.x), "=f"(r.y) : "l"(v)); return r;
}

// ---------------------------------------------------------------------------
// Mask dtype detection + normalization (unchanged, verified)
// ---------------------------------------------------------------------------
__global__ __launch_bounds__(256) void detect_mask_kernel(const uint32_t* __restrict__ raw)
{
    __shared__ int sflags[256];
    int f = 0;
    const int tid = threadIdx.x;
    #pragma unroll
    for (int i = 0; i < 16; i++) {
        const uint32_t w = raw[tid * 16 + i];
        if (w != 0u && w != 1u)          f |= 1;
        if (w != 0u && w != 0x3F800000u) f |= 2;
    }
    sflags[tid] = f;
    __syncthreads();
    for (int s = 128; s > 0; s >>= 1) {
        if (tid < s) sflags[tid] |= sflags[tid + s];
        __syncthreads();
    }
    if (tid == 0) g_mask_flags = sflags[0];
}

__global__ __launch_bounds__(256) void convert_mask_kernel(const void* __restrict__ raw)
{
    const int flags = g_mask_flags;
    const size_t i0 = ((size_t)blockIdx.x * 256 + threadIdx.x) * 4;
    if (i0 >= MASK_N) return;
    uchar4 o;
    if ((flags & 1) == 0) {              // int32
        const int4 v = *reinterpret_cast<const int4*>((const int*)raw + i0);
        o = make_uchar4(v.x != 0, v.y != 0, v.z != 0, v.w != 0);
    } else if ((flags & 2) == 0) {       // float32
        const float4 v = *reinterpret_cast<const float4*>((const float*)raw + i0);
        o = make_uchar4(v.x != 0.f, v.y != 0.f, v.z != 0.f, v.w != 0.f);
    } else {                             // uint8 bool
        o = *reinterpret_cast<const uchar4*>((const uint8_t*)raw + i0);
        o = make_uchar4(o.x != 0, o.y != 0, o.z != 0, o.w != 0);
    }
    *reinterpret_cast<uchar4*>(g_mask + i0) = o;
}

// ---------------------------------------------------------------------------
// GEMM: out = (op(A) @ W^T + bias) * scale        (FFMA2 inner loop)
//   A: [M=4096, K=1024]; W: [N=1024, K=1024] row-major; bias: [N]
//   amode 0: A plain row-major.  amode 1: A gathered from [B,H,S,DH].
//   omode 0: out plain [M,N].
//   omode 1: out scattered to [B,H,S,DH] (natural head layout).
//   omode 2: out scattered to [B,H,DH,S] (transposed head layout).
// ---------------------------------------------------------------------------
__global__ __launch_bounds__(256) void gemm_kernel(
    const float* __restrict__ A, const float* __restrict__ W,
    const float* __restrict__ bias, float* __restrict__ out,
    int amode, int omode, float scale)
{
    __shared__ float As[16][68];
    __shared__ float Ws[16][68];

    const int K = D_;
    const int tid  = threadIdx.x;
    const int row0 = blockIdx.y * 64;
    const int col0 = blockIdx.x * 64;

    const int lr  = tid >> 2;
    const int lc4 = (tid & 3) * 4;
    const int ty  = tid >> 4;
    const int tx  = tid & 15;

    uint64_t acc2[4][2];
    #pragma unroll
    for (int i = 0; i < 4; i++) { acc2[i][0] = 0ull; acc2[i][1] = 0ull; }

    for (int k0 = 0; k0 < K; k0 += 16) {
        float4 av;
        {
            const int arow = row0 + lr;
            const int kk   = k0 + lc4;
            if (amode == 0) {
                av = *reinterpret_cast<const float4*>(A + (size_t)arow * K + kk);
            } else {
                const int b = arow >> 11, s = arow & (S_ - 1);
                const int h = kk >> 6,  dh = kk & 63;
                av = *reinterpret_cast<const float4*>(
                    A + ((((size_t)b * H_ + h) * S_ + s) << 6) + dh);
            }
        }
        As[lc4 + 0][lr] = av.x; As[lc4 + 1][lr] = av.y;
        As[lc4 + 2][lr] = av.z; As[lc4 + 3][lr] = av.w;

        {
            const float4 wv = *reinterpret_cast<const float4*>(
                W + (size_t)(col0 + lr) * K + k0 + lc4);
            Ws[lc4 + 0][lr] = wv.x; Ws[lc4 + 1][lr] = wv.y;
            Ws[lc4 + 2][lr] = wv.z; Ws[lc4 + 3][lr] = wv.w;
        }
        __syncthreads();

        #pragma unroll
        for (int kk = 0; kk < 16; kk++) {
            const float4 a4 = *reinterpret_cast<const float4*>(&As[kk][ty * 4]);
            const ulonglong2 w2 = *reinterpret_cast<const ulonglong2*>(&Ws[kk][tx * 4]);
            const float a_[4] = {a4.x, a4.y, a4.z, a4.w};
            #pragma unroll
            for (int i = 0; i < 4; i++) {
                const uint64_t ai = dup2(a_[i]);
                ffma2(acc2[i][0], ai, w2.x);
                ffma2(acc2[i][1], ai, w2.y);
            }
        }
        __syncthreads();
    }

    // epilogue
    const float4 bv = *reinterpret_cast<const float4*>(bias + col0 + tx * 4);
    #pragma unroll
    for (int i = 0; i < 4; i++) {
        const int m = row0 + ty * 4 + i;
        const float2 lo = unpack2(acc2[i][0]);
        const float2 hi = unpack2(acc2[i][1]);
        float4 o;
        o.x = (lo.x + bv.x) * scale;
        o.y = (lo.y + bv.y) * scale;
        o.z = (hi.x + bv.z) * scale;
        o.w = (hi.y + bv.w) * scale;
        if (omode == 0) {
            *reinterpret_cast<float4*>(out + (size_t)m * D_ + col0 + tx * 4) = o;
        } else if (omode == 1) {
            const int n = col0 + tx * 4;
            const int b = m >> 11, s = m & (S_ - 1);
            const int h = n >> 6,  dh = n & 63;
            *reinterpret_cast<float4*>(
                out + ((((size_t)b * H_ + h) * S_ + s) << 6) + dh) = o;
        } else {
            // transposed head layout [B,H,DH,S]
            const int b = m >> 11, s = m & (S_ - 1);
            const float oj[4] = {o.x, o.y, o.z, o.w};
            #pragma unroll
            for (int j = 0; j < 4; j++) {
                const int n = col0 + tx * 4 + j;
                const int h = n >> 6, dh = n & 63;
                out[(((size_t)b * H_ + h) * DH_ + dh) * S_ + s] = oj[j];
            }
        }
    }
}

// ---------------------------------------------------------------------------
// Flash attention v3: 64q x 64k tiles, 256 threads, 4x4 register blocking,
// packed FFMA2. Q,K read from transposed [B,H,DH,S]; V natural [B,H,S,DH].
// ---------------------------------------------------------------------------
#define FLD 68

__global__ __launch_bounds__(256) void flash_kernel()
{
    extern __shared__ float sm[];
    float* Qs = sm;                   // [64 d][64 q]
    float* Ks = Qs + 64 * FLD;        // [64 d][64 k]
    float* Vs = Ks + 64 * FLD;        // [64 k][64 d]
    float* Ps = Vs + 64 * FLD;        // [64 k][64 q]

    const int tid = threadIdx.x;
    const int q0  = blockIdx.x * 64;
    const int h   = blockIdx.y;
    const int b   = blockIdx.z;
    const size_t tbase = ((size_t)b * H_ + h) * DH_ * S_;  // transposed Q/K base
    const size_t vbase = ((size_t)b * H_ + h) * S_ * DH_;  // natural V/ctx base

    const int ty = tid >> 4;   // 0..15 (q groups of 4)
    const int tx = tid & 15;   // 0..15 (k / d groups of 4)

    // load Q tile (d-major, coalesced along q)
    #pragma unroll
    for (int i = 0; i < 4; i++) {
        const int f = tid + i * 256;
        const int d = f >> 4, c4 = (f & 15) << 2;
        *reinterpret_cast<float4*>(Qs + d * FLD + c4) =
            *reinterpret_cast<const float4*>(g_q + tbase + (size_t)d * S_ + q0 + c4);
    }

    uint64_t o2[4][2];
    #pragma unroll
    for (int i = 0; i < 4; i++) { o2[i][0] = 0ull; o2[i][1] = 0ull; }
    float m_i[4], l_i[4];
    #pragma unroll
    for (int i = 0; i < 4; i++) { m_i[i] = -CUDART_INF_F; l_i[i] = 0.f; }

    __syncthreads();

    for (int kt = 0; kt < S_ / 64; kt++) {
        const int k0 = kt * 64;
        // load K (d-major) and V (k-major)
        #pragma unroll
        for (int i = 0; i < 4; i++) {
            const int f = tid + i * 256;
            const int rr = f >> 4, c4 = (f & 15) << 2;
            *reinterpret_cast<float4*>(Ks + rr * FLD + c4) =
                *reinterpret_cast<const float4*>(g_k + tbase + (size_t)rr * S_ + k0 + c4);
            *reinterpret_cast<float4*>(Vs + rr * FLD + c4) =
                *reinterpret_cast<const float4*>(g_v + vbase + (size_t)(k0 + rr) * DH_ + c4);
        }
        __syncthreads();

        // scores: s2[i] = q_{ty*4+i} . k_{tx*4 .. +3}   (outer product over d)
        uint64_t s2[4][2];
        #pragma unroll
        for (int i = 0; i < 4; i++) { s2[i][0] = 0ull; s2[i][1] = 0ull; }
        #pragma unroll 16
        for (int d = 0; d < 64; d++) {
            const float4 q4 = *reinterpret_cast<const float4*>(Qs + d * FLD + ty * 4);
            const ulonglong2 k2 = *reinterpret_cast<const ulonglong2*>(Ks + d * FLD + tx * 4);
            const float q_[4] = {q4.x, q4.y, q4.z, q4.w};
            #pragma unroll
            for (int i = 0; i < 4; i++) {
                const uint64_t ai = dup2(q_[i]);
                ffma2(s2[i][0], ai, k2.x);
                ffma2(s2[i][1], ai, k2.y);
            }
        }

        // unpack + mask
        float sc[4][4];
        #pragma unroll
        for (int i = 0; i < 4; i++) {
            const float2 lo = unpack2(s2[i][0]);
            const float2 hi = unpack2(s2[i][1]);
            sc[i][0] = lo.x; sc[i][1] = lo.y; sc[i][2] = hi.x; sc[i][3] = hi.y;
            const uchar4 mv = *reinterpret_cast<const uchar4*>(
                g_mask + ((size_t)b * S_ + (q0 + ty * 4 + i)) * S_ + k0 + tx * 4);
            if (mv.x) sc[i][0] = -1e18f;
            if (mv.y) sc[i][1] = -1e18f;
            if (mv.z) sc[i][2] = -1e18f;
            if (mv.w) sc[i][3] = -1e18f;
        }

        // online softmax per row (reduce across 16 tx lanes: half-warp groups)
        #pragma unroll
        for (int i = 0; i < 4; i++) {
            float rmax = fmaxf(fmaxf(sc[i][0], sc[i][1]), fmaxf(sc[i][2], sc[i][3]));
            rmax = fmaxf(rmax, __shfl_xor_sync(0xffffffffu, rmax, 1));
            rmax = fmaxf(rmax, __shfl_xor_sync(0xffffffffu, rmax, 2));
            rmax = fmaxf(rmax, __shfl_xor_sync(0xffffffffu, rmax, 4));
            rmax = fmaxf(rmax, __shfl_xor_sync(0xffffffffu, rmax, 8));

            const float mn = fmaxf(m_i[i], rmax);
            const float alpha = __expf(m_i[i] - mn);
            float rsum = 0.f;
            #pragma unroll
            for (int j = 0; j < 4; j++) { sc[i][j] = __expf(sc[i][j] - mn); rsum += sc[i][j]; }
            rsum += __shfl_xor_sync(0xffffffffu, rsum, 1);
            rsum += __shfl_xor_sync(0xffffffffu, rsum, 2);
            rsum += __shfl_xor_sync(0xffffffffu, rsum, 4);
            rsum += __shfl_xor_sync(0xffffffffu, rsum, 8);

            l_i[i] = l_i[i] * alpha + rsum;
            m_i[i] = mn;
            const uint64_t ua = dup2(alpha);
            fmul2(o2[i][0], ua);
            fmul2(o2[i][1], ua);
        }

        // store P transposed: Ps[k][q]
        #pragma unroll
        for (int j = 0; j < 4; j++) {
            *reinterpret_cast<float4*>(Ps + (tx * 4 + j) * FLD + ty * 4) =
                make_float4(sc[0][j], sc[1][j], sc[2][j], sc[3][j]);
        }
        __syncthreads();

        // O += P @ V  (outer product over keys c)
        #pragma unroll 16
        for (int c = 0; c < 64; c++) {
            const float4 p4 = *reinterpret_cast<const float4*>(Ps + c * FLD + ty * 4);
            const ulonglong2 v2 = *reinterpret_cast<const ulonglong2*>(Vs + c * FLD + tx * 4);
            const float p_[4] = {p4.x, p4.y, p4.z, p4.w};
            #pragma unroll
            for (int i = 0; i < 4; i++) {
                const uint64_t ai = dup2(p_[i]);
                ffma2(o2[i][0], ai, v2.x);
                ffma2(o2[i][1], ai, v2.y);
            }
        }
        __syncthreads();
    }

    // finalize: ctx (natural head layout)
    #pragma unroll
    for (int i = 0; i < 4; i++) {
        const float inv = 1.f / l_i[i];
        const float2 lo = unpack2(o2[i][0]);
        const float2 hi = unpack2(o2[i][1]);
        const float4 v = make_float4(lo.x * inv, lo.y * inv, hi.x * inv, hi.y * inv);
        *reinterpret_cast<float4*>(
            g_ctx + vbase + (size_t)(q0 + ty * 4 + i) * DH_ + tx * 4) = v;
    }
}

// ---------------------------------------------------------------------------
extern "C" void kernel_launch(void* const* d_in, const int* in_sizes, int n_in,
                              void* d_out, int out_size)
{
    const float* key   = (const float*)d_in[0];
    const float* value = (const float*)d_in[1];
    const float* query = (const float*)d_in[2];
    const void*  mask  = d_in[3];
    const float* Wq = (const float*)d_in[4];
    const float* bq = (const float*)d_in[5];
    const float* Wk = (const float*)d_in[6];
    const float* bk = (const float*)d_in[7];
    const float* Wv = (const float*)d_in[8];
    const float* bv = (const float*)d_in[9];
    const float* Wo = (const float*)d_in[10];
    const float* bo = (const float*)d_in[11];
    float* out = (float*)d_out;

    void *pq, *pk, *pv, *pctx;
    cudaGetSymbolAddress(&pq,   g_q);
    cudaGetSymbolAddress(&pk,   g_k);
    cudaGetSymbolAddress(&pv,   g_v);
    cudaGetSymbolAddress(&pctx, g_ctx);

    // mask normalization (dtype-agnostic)
    detect_mask_kernel<<<1, 256>>>((const uint32_t*)mask);
    convert_mask_kernel<<<(MASK_N / 4 + 255) / 256, 256>>>(mask);

    const dim3 gb(D_ / 64, MTOT / 64);   // (16, 64)

    // projections: Q,K written transposed [B,H,DH,S] (omode 2); V natural (omode 1).
    // Q pre-scaled by 1/sqrt(DH) = 0.125
    gemm_kernel<<<gb, 256>>>(query, Wq, bq, (float*)pq, 0, 2, 0.125f);
    gemm_kernel<<<gb, 256>>>(key,   Wk, bk, (float*)pk, 0, 2, 1.f);
    gemm_kernel<<<gb, 256>>>(value, Wv, bv, (float*)pv, 0, 1, 1.f);

    // attention
    const size_t smem = (size_t)4 * 64 * FLD * sizeof(float);   // 69632 B
    cudaFuncSetAttribute(flash_kernel,
                         cudaFuncAttributeMaxDynamicSharedMemorySize, (int)smem);
    flash_kernel<<<dim3(S_ / 64, H_, B_), 256, smem>>>();

    // output projection (gather from natural head layout)
    gemm_kernel<<<gb, 256>>>((const float*)pctx, Wo, bo, out, 1, 0, 1.f);
}

// round 5
// speedup vs baseline: 4.4650x; 2.1151x over previous
#include <cuda_runtime.h>
#include <cuda_bf16.h>
#include <stdint.h>
#include <math_constants.h>

// Problem constants
#define B_   2
#define S_   2048
#define D_   1024
#define H_   16
#define DH_  64
#define MTOT (B_ * S_)          // 4096
#define MASK_N (B_ * S_ * S_)   // 8388608
#define KSPLIT 3072             // K' = 3*1024 (bf16 split folded into K)

// Scratch (device globals — allocation-free per harness rules)
__device__ float   g_q[MTOT * D_];    // transposed head layout [B,H,DH,S]
__device__ float   g_k[MTOT * D_];    // transposed head layout [B,H,DH,S]
__device__ float   g_v[MTOT * D_];    // natural head layout [B,H,S,DH]
__device__ float   g_ctx[MTOT * D_];  // natural head layout [B,H,S,DH]
__device__ uint8_t g_mask[MASK_N];
__device__ int     g_mask_flags;
__device__ unsigned short g_abuf[MTOT * KSPLIT];  // A' bf16 [4096, 3072]
__device__ unsigned short g_wbuf[D_ * KSPLIT];    // W' bf16 [1024, 3072]

// ---------------------------------------------------------------------------
// warp-mma helpers (baseline PTX ISA — legal on plain sm_103)
// ---------------------------------------------------------------------------
__device__ __forceinline__ uint32_t smem_u32(const void* p) {
    uint32_t a;
    asm("{ .reg .u64 t; cvta.to.shared.u64 t, %1; cvt.u32.u64 %0, t; }"
        : "=r"(a) : "l"(p));
    return a;
}
__device__ __forceinline__ void ldsm_x4(uint32_t& r0, uint32_t& r1,
                                        uint32_t& r2, uint32_t& r3, uint32_t addr) {
    asm volatile("ldmatrix.sync.aligned.m8n8.x4.shared.b16 {%0,%1,%2,%3}, [%4];"
                 : "=r"(r0), "=r"(r1), "=r"(r2), "=r"(r3) : "r"(addr));
}
__device__ __forceinline__ void ldsm_x2(uint32_t& r0, uint32_t& r1, uint32_t addr) {
    asm volatile("ldmatrix.sync.aligned.m8n8.x2.shared.b16 {%0,%1}, [%2];"
                 : "=r"(r0), "=r"(r1) : "r"(addr));
}
__device__ __forceinline__ void mma16816(float* c, const uint32_t* a, const uint32_t* b) {
    asm volatile(
        "mma.sync.aligned.m16n8k16.row.col.f32.bf16.bf16.f32 "
        "{%0,%1,%2,%3}, {%4,%5,%6,%7}, {%8,%9}, {%0,%1,%2,%3};"
        : "+f"(c[0]), "+f"(c[1]), "+f"(c[2]), "+f"(c[3])
        : "r"(a[0]), "r"(a[1]), "r"(a[2]), "r"(a[3]), "r"(b[0]), "r"(b[1]));
}

// ---------------------------------------------------------------------------
// Mask dtype detection + normalization (verified in R2)
// ---------------------------------------------------------------------------
__global__ __launch_bounds__(256) void detect_mask_kernel(const uint32_t* __restrict__ raw)
{
    __shared__ int sflags[256];
    int f = 0;
    const int tid = threadIdx.x;
    #pragma unroll
    for (int i = 0; i < 16; i++) {
        const uint32_t w = raw[tid * 16 + i];
        if (w != 0u && w != 1u)          f |= 1;
        if (w != 0u && w != 0x3F800000u) f |= 2;
    }
    sflags[tid] = f;
    __syncthreads();
    for (int s = 128; s > 0; s >>= 1) {
        if (tid < s) sflags[tid] |= sflags[tid + s];
        __syncthreads();
    }
    if (tid == 0) g_mask_flags = sflags[0];
}

__global__ __launch_bounds__(256) void convert_mask_kernel(const void* __restrict__ raw)
{
    const int flags = g_mask_flags;
    const size_t i0 = ((size_t)blockIdx.x * 256 + threadIdx.x) * 4;
    if (i0 >= MASK_N) return;
    uchar4 o;
    if ((flags & 1) == 0) {
        const int4 v = *reinterpret_cast<const int4*>((const int*)raw + i0);
        o = make_uchar4(v.x != 0, v.y != 0, v.z != 0, v.w != 0);
    } else if ((flags & 2) == 0) {
        const float4 v = *reinterpret_cast<const float4*>((const float*)raw + i0);
        o = make_uchar4(v.x != 0.f, v.y != 0.f, v.z != 0.f, v.w != 0.f);
    } else {
        o = *reinterpret_cast<const uchar4*>((const uint8_t*)raw + i0);
        o = make_uchar4(o.x != 0, o.y != 0, o.z != 0, o.w != 0);
    }
    *reinterpret_cast<uchar4*>(g_mask + i0) = o;
}

// ---------------------------------------------------------------------------
// Split-bf16 conversion:  x = hi + lo (each bf16)
//   A' = [Ahi | Ahi | Alo],  W' = [Whi | Wlo | Whi]   (K'=3072)
// => A'·W'^T = AhiWhi + AhiWlo + AloWhi  (~fp32 accuracy, fp32 accum)
// ---------------------------------------------------------------------------
__device__ __forceinline__ unsigned short f2bf(float x) {
    return __bfloat16_as_ushort(__float2bfloat16_rn(x));
}
__device__ __forceinline__ float bf2f(unsigned short u) {
    return __bfloat162float(__ushort_as_bfloat16(u));
}

__global__ __launch_bounds__(256) void split_A_kernel(const float* __restrict__ A, int gather)
{
    const int t  = blockIdx.x * 256 + threadIdx.x;
    const int e0 = t * 4;
    const int m  = e0 >> 10, k = e0 & 1023;
    float4 v;
    if (!gather) {
        v = *reinterpret_cast<const float4*>(A + (size_t)m * D_ + k);
    } else {
        const int b = m >> 11, s = m & (S_ - 1);
        const int h = k >> 6, dh = k & 63;
        v = *reinterpret_cast<const float4*>(
            A + ((((size_t)b * H_ + h) * S_ + s) << 6) + dh);
    }
    ushort4 hi = make_ushort4(f2bf(v.x), f2bf(v.y), f2bf(v.z), f2bf(v.w));
    ushort4 lo = make_ushort4(f2bf(v.x - bf2f(hi.x)), f2bf(v.y - bf2f(hi.y)),
                              f2bf(v.z - bf2f(hi.z)), f2bf(v.w - bf2f(hi.w)));
    const size_t base = (size_t)m * KSPLIT;
    *reinterpret_cast<ushort4*>(g_abuf + base + k)        = hi;
    *reinterpret_cast<ushort4*>(g_abuf + base + 1024 + k) = hi;
    *reinterpret_cast<ushort4*>(g_abuf + base + 2048 + k) = lo;
}

__global__ __launch_bounds__(256) void split_W_kernel(const float* __restrict__ W)
{
    const int t  = blockIdx.x * 256 + threadIdx.x;
    const int e0 = t * 4;
    const int n  = e0 >> 10, k = e0 & 1023;
    const float4 v = *reinterpret_cast<const float4*>(W + (size_t)n * D_ + k);
    ushort4 hi = make_ushort4(f2bf(v.x), f2bf(v.y), f2bf(v.z), f2bf(v.w));
    ushort4 lo = make_ushort4(f2bf(v.x - bf2f(hi.x)), f2bf(v.y - bf2f(hi.y)),
                              f2bf(v.z - bf2f(hi.z)), f2bf(v.w - bf2f(hi.w)));
    const size_t base = (size_t)n * KSPLIT;
    *reinterpret_cast<ushort4*>(g_wbuf + base + k)        = hi;
    *reinterpret_cast<ushort4*>(g_wbuf + base + 1024 + k) = lo;
    *reinterpret_cast<ushort4*>(g_wbuf + base + 2048 + k) = hi;
}

// ---------------------------------------------------------------------------
// HMMA GEMM: C[4096, 1024] = A'[4096, 3072] @ W'[1024, 3072]^T (bf16, f32 acc)
// CTA 128x128, 8 warps (2m x 4n), warp tile 64x32 (4x4 m16n8k16 frags),
// BK=32, double-buffered smem, ldmatrix feeds, one sync per chunk.
//   omode 0: out plain [M, N] (+bias)*scale
//   omode 1: scattered to [B,H,S,DH]
//   omode 2: scattered to [B,H,DH,S]
// ---------------------------------------------------------------------------
#define BK    32
#define SST   40                     // smem row stride (bf16)
#define SMATE (128 * SST)            // elems per matrix per stage
#define STAGE (2 * SMATE)            // elems per stage (A then B)
#define NCHUNK (KSPLIT / BK)         // 96

__global__ __launch_bounds__(256, 1) void mma_gemm_kernel(
    const unsigned short* __restrict__ Abuf, const unsigned short* __restrict__ Wbuf,
    const float* __restrict__ bias, float* __restrict__ out,
    int omode, float scale)
{
    __shared__ __align__(16) unsigned short sbuf[2 * STAGE];  // 40960 B

    const int tid  = threadIdx.x;
    const int wid  = tid >> 5, lane = tid & 31;
    const int wm   = wid >> 2, wn = wid & 3;       // warp grid 2 x 4
    const int m0   = blockIdx.y * 128, n0 = blockIdx.x * 128;

    const uint32_t sb = smem_u32(sbuf);

    float acc[4][4][4];
    #pragma unroll
    for (int i = 0; i < 4; i++)
        #pragma unroll
        for (int j = 0; j < 4; j++)
            #pragma unroll
            for (int e = 0; e < 4; e++) acc[i][j][e] = 0.f;

    // per-thread load coords: 2 segments each for A and B per stage
    const int lrow0 = tid >> 2, lseg = (tid & 3) * 8;   // rows 0..63, seg 0/8/16/24
    // (second segment: rows 64..127)

    // preload stage 0
    {
        const unsigned short* Ap = Abuf + (size_t)(m0 + lrow0) * KSPLIT + lseg;
        const unsigned short* Bp = Wbuf + (size_t)(n0 + lrow0) * KSPLIT + lseg;
        *reinterpret_cast<uint4*>(sbuf + lrow0 * SST + lseg) =
            *reinterpret_cast<const uint4*>(Ap);
        *reinterpret_cast<uint4*>(sbuf + (lrow0 + 64) * SST + lseg) =
            *reinterpret_cast<const uint4*>(Ap + (size_t)64 * KSPLIT);
        *reinterpret_cast<uint4*>(sbuf + SMATE + lrow0 * SST + lseg) =
            *reinterpret_cast<const uint4*>(Bp);
        *reinterpret_cast<uint4*>(sbuf + SMATE + (lrow0 + 64) * SST + lseg) =
            *reinterpret_cast<const uint4*>(Bp + (size_t)64 * KSPLIT);
    }
    __syncthreads();

    // ldmatrix address components (byte offsets within a stage)
    const int a_row = wm * 64 + (lane & 15);
    const int a_colh = (lane >> 4) * 8;
    const int b_row = wn * 32 + (lane & 7);
    const int b_colh = ((lane >> 3) & 1) * 8;

    for (int c = 0; c < NCHUNK; c++) {
        const int st = c & 1;
        const uint32_t sa = sb + (uint32_t)(st * STAGE) * 2;
        const uint32_t sbm = sa + (uint32_t)SMATE * 2;

        uint4 pa0, pa1, pb0, pb1;
        if (c + 1 < NCHUNK) {
            const int k0 = (c + 1) * BK;
            const unsigned short* Ap = Abuf + (size_t)(m0 + lrow0) * KSPLIT + k0 + lseg;
            const unsigned short* Bp = Wbuf + (size_t)(n0 + lrow0) * KSPLIT + k0 + lseg;
            pa0 = *reinterpret_cast<const uint4*>(Ap);
            pa1 = *reinterpret_cast<const uint4*>(Ap + (size_t)64 * KSPLIT);
            pb0 = *reinterpret_cast<const uint4*>(Bp);
            pb1 = *reinterpret_cast<const uint4*>(Bp + (size_t)64 * KSPLIT);
        }

        #pragma unroll
        for (int ks = 0; ks < 2; ks++) {
            uint32_t a[4][4], b[4][2];
            #pragma unroll
            for (int mt = 0; mt < 4; mt++) {
                const uint32_t addr = sa +
                    ((a_row + mt * 16) * SST + ks * 16 + a_colh) * 2;
                ldsm_x4(a[mt][0], a[mt][1], a[mt][2], a[mt][3], addr);
            }
            #pragma unroll
            for (int nt = 0; nt < 4; nt++) {
                const uint32_t addr = sbm +
                    ((b_row + nt * 8) * SST + ks * 16 + b_colh) * 2;
                ldsm_x2(b[nt][0], b[nt][1], addr);
            }
            #pragma unroll
            for (int mt = 0; mt < 4; mt++)
                #pragma unroll
                for (int nt = 0; nt < 4; nt++)
                    mma16816(acc[mt][nt], a[mt], b[nt]);
        }

        if (c + 1 < NCHUNK) {
            unsigned short* d = sbuf + (st ^ 1) * STAGE;
            *reinterpret_cast<uint4*>(d + lrow0 * SST + lseg) = pa0;
            *reinterpret_cast<uint4*>(d + (lrow0 + 64) * SST + lseg) = pa1;
            *reinterpret_cast<uint4*>(d + SMATE + lrow0 * SST + lseg) = pb0;
            *reinterpret_cast<uint4*>(d + SMATE + (lrow0 + 64) * SST + lseg) = pb1;
        }
        __syncthreads();
    }

    // epilogue: fragment layout m16n8 — thread (lane): rows gr, gr+8; cols gc, gc+1
    const int gr = lane >> 2, gc = (lane & 3) * 2;
    #pragma unroll
    for (int mt = 0; mt < 4; mt++) {
        #pragma unroll
        for (int nt = 0; nt < 4; nt++) {
            const int n = n0 + wn * 32 + nt * 8 + gc;
            const float b0 = bias[n], b1 = bias[n + 1];
            #pragma unroll
            for (int half = 0; half < 2; half++) {
                const int m = m0 + wm * 64 + mt * 16 + gr + half * 8;
                const float v0 = (acc[mt][nt][half * 2 + 0] + b0) * scale;
                const float v1 = (acc[mt][nt][half * 2 + 1] + b1) * scale;
                if (omode == 0) {
                    float2* p = reinterpret_cast<float2*>(out + (size_t)m * D_ + n);
                    *p = make_float2(v0, v1);
                } else if (omode == 1) {
                    const int b = m >> 11, s = m & (S_ - 1);
                    const int h = n >> 6, dh = n & 63;
                    float2* p = reinterpret_cast<float2*>(
                        out + (((size_t)b * H_ + h) * S_ + s) * DH_ + dh);
                    *p = make_float2(v0, v1);   // dh, dh+1 contiguous (n%64 = gc even, <63)
                } else {
                    const int b = m >> 11, s = m & (S_ - 1);
                    const int h = n >> 6, dh = n & 63;
                    out[(((size_t)b * H_ + h) * DH_ + dh) * S_ + s] = v0;
                    out[(((size_t)b * H_ + h) * DH_ + dh + 1) * S_ + s] = v1;
                }
            }
        }
    }
}

// ---------------------------------------------------------------------------
// Flash attention: 64q x 64k tiles, 256 threads, 4x4 register blocking, scalar
// FMA. Q,K transposed [B,H,DH,S]; V natural [B,H,S,DH].
// ---------------------------------------------------------------------------
#define FLD 68

__global__ __launch_bounds__(256) void flash_kernel()
{
    extern __shared__ float sm[];
    float* Qs = sm;                   // [64 d][64 q]
    float* Ks = Qs + 64 * FLD;        // [64 d][64 k]
    float* Vs = Ks + 64 * FLD;        // [64 k][64 d]
    float* Ps = Vs + 64 * FLD;        // [64 k][64 q]

    const int tid = threadIdx.x;
    const int q0  = blockIdx.x * 64;
    const int h   = blockIdx.y;
    const int b   = blockIdx.z;
    const size_t tbase = ((size_t)b * H_ + h) * DH_ * S_;
    const size_t vbase = ((size_t)b * H_ + h) * S_ * DH_;

    const int ty = tid >> 4;
    const int tx = tid & 15;

    #pragma unroll
    for (int i = 0; i < 4; i++) {
        const int f = tid + i * 256;
        const int d = f >> 4, c4 = (f & 15) << 2;
        *reinterpret_cast<float4*>(Qs + d * FLD + c4) =
            *reinterpret_cast<const float4*>(g_q + tbase + (size_t)d * S_ + q0 + c4);
    }

    float o_[4][4];
    #pragma unroll
    for (int i = 0; i < 4; i++)
        #pragma unroll
        for (int j = 0; j < 4; j++) o_[i][j] = 0.f;
    float m_i[4], l_i[4];
    #pragma unroll
    for (int i = 0; i < 4; i++) { m_i[i] = -CUDART_INF_F; l_i[i] = 0.f; }

    __syncthreads();

    for (int kt = 0; kt < S_ / 64; kt++) {
        const int k0 = kt * 64;
        #pragma unroll
        for (int i = 0; i < 4; i++) {
            const int f = tid + i * 256;
            const int rr = f >> 4, c4 = (f & 15) << 2;
            *reinterpret_cast<float4*>(Ks + rr * FLD + c4) =
                *reinterpret_cast<const float4*>(g_k + tbase + (size_t)rr * S_ + k0 + c4);
            *reinterpret_cast<float4*>(Vs + rr * FLD + c4) =
                *reinterpret_cast<const float4*>(g_v + vbase + (size_t)(k0 + rr) * DH_ + c4);
        }
        __syncthreads();

        float sc[4][4];
        #pragma unroll
        for (int i = 0; i < 4; i++)
            #pragma unroll
            for (int j = 0; j < 4; j++) sc[i][j] = 0.f;
        #pragma unroll 8
        for (int d = 0; d < 64; d++) {
            const float4 q4 = *reinterpret_cast<const float4*>(Qs + d * FLD + ty * 4);
            const float4 k4 = *reinterpret_cast<const float4*>(Ks + d * FLD + tx * 4);
            const float q_[4] = {q4.x, q4.y, q4.z, q4.w};
            const float k_[4] = {k4.x, k4.y, k4.z, k4.w};
            #pragma unroll
            for (int i = 0; i < 4; i++)
                #pragma unroll
                for (int j = 0; j < 4; j++)
                    sc[i][j] = fmaf(q_[i], k_[j], sc[i][j]);
        }

        #pragma unroll
        for (int i = 0; i < 4; i++) {
            const uchar4 mv = *reinterpret_cast<const uchar4*>(
                g_mask + ((size_t)b * S_ + (q0 + ty * 4 + i)) * S_ + k0 + tx * 4);
            if (mv.x) sc[i][0] = -1e18f;
            if (mv.y) sc[i][1] = -1e18f;
            if (mv.z) sc[i][2] = -1e18f;
            if (mv.w) sc[i][3] = -1e18f;
        }

        #pragma unroll
        for (int i = 0; i < 4; i++) {
            float rmax = fmaxf(fmaxf(sc[i][0], sc[i][1]), fmaxf(sc[i][2], sc[i][3]));
            rmax = fmaxf(rmax, __shfl_xor_sync(0xffffffffu, rmax, 1));
            rmax = fmaxf(rmax, __shfl_xor_sync(0xffffffffu, rmax, 2));
            rmax = fmaxf(rmax, __shfl_xor_sync(0xffffffffu, rmax, 4));
            rmax = fmaxf(rmax, __shfl_xor_sync(0xffffffffu, rmax, 8));

            const float mn = fmaxf(m_i[i], rmax);
            const float alpha = __expf(m_i[i] - mn);
            float rsum = 0.f;
            #pragma unroll
            for (int j = 0; j < 4; j++) { sc[i][j] = __expf(sc[i][j] - mn); rsum += sc[i][j]; }
            rsum += __shfl_xor_sync(0xffffffffu, rsum, 1);
            rsum += __shfl_xor_sync(0xffffffffu, rsum, 2);
            rsum += __shfl_xor_sync(0xffffffffu, rsum, 4);
            rsum += __shfl_xor_sync(0xffffffffu, rsum, 8);

            l_i[i] = l_i[i] * alpha + rsum;
            m_i[i] = mn;
            #pragma unroll
            for (int j = 0; j < 4; j++) o_[i][j] *= alpha;
        }

        #pragma unroll
        for (int j = 0; j < 4; j++) {
            *reinterpret_cast<float4*>(Ps + (tx * 4 + j) * FLD + ty * 4) =
                make_float4(sc[0][j], sc[1][j], sc[2][j], sc[3][j]);
        }
        __syncthreads();

        #pragma unroll 8
        for (int c = 0; c < 64; c++) {
            const float4 p4 = *reinterpret_cast<const float4*>(Ps + c * FLD + ty * 4);
            const float4 v4 = *reinterpret_cast<const float4*>(Vs + c * FLD + tx * 4);
            const float p_[4] = {p4.x, p4.y, p4.z, p4.w};
            const float v_[4] = {v4.x, v4.y, v4.z, v4.w};
            #pragma unroll
            for (int i = 0; i < 4; i++)
                #pragma unroll
                for (int j = 0; j < 4; j++)
                    o_[i][j] = fmaf(p_[i], v_[j], o_[i][j]);
        }
        __syncthreads();
    }

    #pragma unroll
    for (int i = 0; i < 4; i++) {
        const float inv = 1.f / l_i[i];
        const float4 v = make_float4(o_[i][0] * inv, o_[i][1] * inv,
                                     o_[i][2] * inv, o_[i][3] * inv);
        *reinterpret_cast<float4*>(
            g_ctx + vbase + (size_t)(q0 + ty * 4 + i) * DH_ + tx * 4) = v;
    }
}

// ---------------------------------------------------------------------------
extern "C" void kernel_launch(void* const* d_in, const int* in_sizes, int n_in,
                              void* d_out, int out_size)
{
    const float* key   = (const float*)d_in[0];
    const float* value = (const float*)d_in[1];
    const float* query = (const float*)d_in[2];
    const void*  mask  = d_in[3];
    const float* Wq = (const float*)d_in[4];
    const float* bq = (const float*)d_in[5];
    const float* Wk = (const float*)d_in[6];
    const float* bk = (const float*)d_in[7];
    const float* Wv = (const float*)d_in[8];
    const float* bv = (const float*)d_in[9];
    const float* Wo = (const float*)d_in[10];
    const float* bo = (const float*)d_in[11];
    float* out = (float*)d_out;

    void *pq, *pk, *pv, *pctx, *pa, *pw;
    cudaGetSymbolAddress(&pq,   g_q);
    cudaGetSymbolAddress(&pk,   g_k);
    cudaGetSymbolAddress(&pv,   g_v);
    cudaGetSymbolAddress(&pctx, g_ctx);
    cudaGetSymbolAddress(&pa,   g_abuf);
    cudaGetSymbolAddress(&pw,   g_wbuf);
    const unsigned short* abuf = (const unsigned short*)pa;
    const unsigned short* wbuf = (const unsigned short*)pw;

    // mask normalization (dtype-agnostic)
    detect_mask_kernel<<<1, 256>>>((const uint32_t*)mask);
    convert_mask_kernel<<<(MASK_N / 4 + 255) / 256, 256>>>(mask);

    const dim3 gg(D_ / 128, MTOT / 128);   // (8, 32)
    const int ga = (MTOT * D_ / 4) / 256;  // 4096 blocks
    const int gw = (D_ * D_ / 4) / 256;    // 1024 blocks

    // Q projection -> transposed [B,H,DH,S], pre-scaled by 1/sqrt(DH)
    split_W_kernel<<<gw, 256>>>(Wq);
    split_A_kernel<<<ga, 256>>>(query, 0);
    mma_gemm_kernel<<<gg, 256>>>(abuf, wbuf, bq, (float*)pq, 2, 0.125f);
    // K projection -> transposed
    split_W_kernel<<<gw, 256>>>(Wk);
    split_A_kernel<<<ga, 256>>>(key, 0);
    mma_gemm_kernel<<<gg, 256>>>(abuf, wbuf, bk, (float*)pk, 2, 1.f);
    // V projection -> natural [B,H,S,DH]
    split_W_kernel<<<gw, 256>>>(Wv);
    split_A_kernel<<<ga, 256>>>(value, 0);
    mma_gemm_kernel<<<gg, 256>>>(abuf, wbuf, bv, (float*)pv, 1, 1.f);

    // attention
    const size_t smem = (size_t)4 * 64 * FLD * sizeof(float);   // 69632 B
    cudaFuncSetAttribute(flash_kernel,
                         cudaFuncAttributeMaxDynamicSharedMemorySize, (int)smem);
    flash_kernel<<<dim3(S_ / 64, H_, B_), 256, smem>>>();

    // output projection (gather ctx from head layout)
    split_W_kernel<<<gw, 256>>>(Wo);
    split_A_kernel<<<ga, 256>>>((const float*)pctx, 1);
    mma_gemm_kernel<<<gg, 256>>>(abuf, wbuf, bo, out, 0, 1.f);
}

// round 6
// speedup vs baseline: 6.9246x; 1.5509x over previous
#include <cuda_runtime.h>
#include <cuda_bf16.h>
#include <stdint.h>
#include <math_constants.h>

// Problem constants
#define B_   2
#define S_   2048
#define D_   1024
#define H_   16
#define DH_  64
#define MTOT (B_ * S_)          // 4096
#define MASK_N (B_ * S_ * S_)   // 8388608
#define KSPLIT 3072             // K' = 3*1024 (bf16 split folded into K)

// Scratch (device globals — allocation-free per harness rules)
__device__ float   g_ctx[MTOT * D_];              // natural head layout [B,H,S,DH]
__device__ uint8_t g_mask[MASK_N];
__device__ int     g_mask_flags;
__device__ unsigned short g_abuf[MTOT * KSPLIT];  // A' bf16 [4096, 3072]
__device__ unsigned short g_wbuf[D_ * KSPLIT];    // W' bf16 [1024, 3072]
__device__ unsigned short g_qhi[MTOT * D_];       // [B,H,S,DH] bf16
__device__ unsigned short g_qlo[MTOT * D_];
__device__ unsigned short g_khi[MTOT * D_];
__device__ unsigned short g_klo[MTOT * D_];
__device__ unsigned short g_vhiT[MTOT * D_];      // [B,H,DH,S] bf16
__device__ unsigned short g_vloT[MTOT * D_];

// ---------------------------------------------------------------------------
// helpers
// ---------------------------------------------------------------------------
__device__ __forceinline__ uint32_t smem_u32(const void* p) {
    uint32_t a;
    asm("{ .reg .u64 t; cvta.to.shared.u64 t, %1; cvt.u32.u64 %0, t; }"
        : "=r"(a) : "l"(p));
    return a;
}
__device__ __forceinline__ void ldsm_x4(uint32_t& r0, uint32_t& r1,
                                        uint32_t& r2, uint32_t& r3, uint32_t addr) {
    asm volatile("ldmatrix.sync.aligned.m8n8.x4.shared.b16 {%0,%1,%2,%3}, [%4];"
                 : "=r"(r0), "=r"(r1), "=r"(r2), "=r"(r3) : "r"(addr));
}
__device__ __forceinline__ void ldsm_x2(uint32_t& r0, uint32_t& r1, uint32_t addr) {
    asm volatile("ldmatrix.sync.aligned.m8n8.x2.shared.b16 {%0,%1}, [%2];"
                 : "=r"(r0), "=r"(r1) : "r"(addr));
}
__device__ __forceinline__ void mma16816(float* c, const uint32_t* a, const uint32_t* b) {
    asm volatile(
        "mma.sync.aligned.m16n8k16.row.col.f32.bf16.bf16.f32 "
        "{%0,%1,%2,%3}, {%4,%5,%6,%7}, {%8,%9}, {%0,%1,%2,%3};"
        : "+f"(c[0]), "+f"(c[1]), "+f"(c[2]), "+f"(c[3])
        : "r"(a[0]), "r"(a[1]), "r"(a[2]), "r"(a[3]), "r"(b[0]), "r"(b[1]));
}
__device__ __forceinline__ void cpa16(uint32_t saddr, const void* g) {
    asm volatile("cp.async.ca.shared.global [%0], [%1], 16;" :: "r"(saddr), "l"(g));
}
__device__ __forceinline__ unsigned short f2bf(float x) {
    return __bfloat16_as_ushort(__float2bfloat16_rn(x));
}
__device__ __forceinline__ float bf2f(unsigned short u) {
    return __bfloat162float(__ushort_as_bfloat16(u));
}
__device__ __forceinline__ uint32_t packbf2(float a, float b) {
    return (uint32_t)f2bf(a) | ((uint32_t)f2bf(b) << 16);
}
// MUFU-free exp: magic round + deg-5 exp2 poly + exponent add. x <= 0 expected.
__device__ __forceinline__ float exp_fast(float x) {
    float y = fmaxf(x * 1.4426950408889634f, -126.0f);
    const float t  = y + 12582912.0f;           // round-to-nearest integer
    const float nf = t - 12582912.0f;
    const float f  = y - nf;
    float p = 0.0013339075f;
    p = fmaf(p, f, 0.0096181691f);
    p = fmaf(p, f, 0.0555041086f);
    p = fmaf(p, f, 0.2402265069f);
    p = fmaf(p, f, 0.6931471806f);
    p = fmaf(p, f, 1.0f);
    return __int_as_float(__float_as_int(p) + (((int)nf) << 23));
}

// ---------------------------------------------------------------------------
// Mask dtype detection + normalization (verified in R2)
// ---------------------------------------------------------------------------
__global__ __launch_bounds__(256) void detect_mask_kernel(const uint32_t* __restrict__ raw)
{
    __shared__ int sflags[256];
    int f = 0;
    const int tid = threadIdx.x;
    #pragma unroll
    for (int i = 0; i < 16; i++) {
        const uint32_t w = raw[tid * 16 + i];
        if (w != 0u && w != 1u)          f |= 1;
        if (w != 0u && w != 0x3F800000u) f |= 2;
    }
    sflags[tid] = f;
    __syncthreads();
    for (int s = 128; s > 0; s >>= 1) {
        if (tid < s) sflags[tid] |= sflags[tid + s];
        __syncthreads();
    }
    if (tid == 0) g_mask_flags = sflags[0];
}

__global__ __launch_bounds__(256) void convert_mask_kernel(const void* __restrict__ raw)
{
    const int flags = g_mask_flags;
    const size_t i0 = ((size_t)blockIdx.x * 256 + threadIdx.x) * 4;
    if (i0 >= MASK_N) return;
    uchar4 o;
    if ((flags & 1) == 0) {
        const int4 v = *reinterpret_cast<const int4*>((const int*)raw + i0);
        o = make_uchar4(v.x != 0, v.y != 0, v.z != 0, v.w != 0);
    } else if ((flags & 2) == 0) {
        const float4 v = *reinterpret_cast<const float4*>((const float*)raw + i0);
        o = make_uchar4(v.x != 0.f, v.y != 0.f, v.z != 0.f, v.w != 0.f);
    } else {
        o = *reinterpret_cast<const uchar4*>((const uint8_t*)raw + i0);
        o = make_uchar4(o.x != 0, o.y != 0, o.z != 0, o.w != 0);
    }
    *reinterpret_cast<uchar4*>(g_mask + i0) = o;
}

// ---------------------------------------------------------------------------
// Split-bf16 conversion:  A' = [hi|hi|lo],  W' = [hi|lo|hi]   (K'=3072)
// ---------------------------------------------------------------------------
__global__ __launch_bounds__(256) void split_A_kernel(const float* __restrict__ A, int gather)
{
    const int t  = blockIdx.x * 256 + threadIdx.x;
    const int e0 = t * 4;
    const int m  = e0 >> 10, k = e0 & 1023;
    float4 v;
    if (!gather) {
        v = *reinterpret_cast<const float4*>(A + (size_t)m * D_ + k);
    } else {
        const int b = m >> 11, s = m & (S_ - 1);
        const int h = k >> 6, dh = k & 63;
        v = *reinterpret_cast<const float4*>(
            A + ((((size_t)b * H_ + h) * S_ + s) << 6) + dh);
    }
    ushort4 hi = make_ushort4(f2bf(v.x), f2bf(v.y), f2bf(v.z), f2bf(v.w));
    ushort4 lo = make_ushort4(f2bf(v.x - bf2f(hi.x)), f2bf(v.y - bf2f(hi.y)),
                              f2bf(v.z - bf2f(hi.z)), f2bf(v.w - bf2f(hi.w)));
    const size_t base = (size_t)m * KSPLIT;
    *reinterpret_cast<ushort4*>(g_abuf + base + k)        = hi;
    *reinterpret_cast<ushort4*>(g_abuf + base + 1024 + k) = hi;
    *reinterpret_cast<ushort4*>(g_abuf + base + 2048 + k) = lo;
}

__global__ __launch_bounds__(256) void split_W_kernel(const float* __restrict__ W)
{
    const int t  = blockIdx.x * 256 + threadIdx.x;
    const int e0 = t * 4;
    const int n  = e0 >> 10, k = e0 & 1023;
    const float4 v = *reinterpret_cast<const float4*>(W + (size_t)n * D_ + k);
    ushort4 hi = make_ushort4(f2bf(v.x), f2bf(v.y), f2bf(v.z), f2bf(v.w));
    ushort4 lo = make_ushort4(f2bf(v.x - bf2f(hi.x)), f2bf(v.y - bf2f(hi.y)),
                              f2bf(v.z - bf2f(hi.z)), f2bf(v.w - bf2f(hi.w)));
    const size_t base = (size_t)n * KSPLIT;
    *reinterpret_cast<ushort4*>(g_wbuf + base + k)        = hi;
    *reinterpret_cast<ushort4*>(g_wbuf + base + 1024 + k) = lo;
    *reinterpret_cast<ushort4*>(g_wbuf + base + 2048 + k) = hi;
}

// ---------------------------------------------------------------------------
// HMMA GEMM: C[m][n] = sum_k A'[m][k]*W'[n][k] (+bias)*scale
// CTA 128x128, 8 warps (2m x 4n), warp tile 64x32, BK=32, double-buffered.
//   omode 0: fp32 out[m][D_ cols]   (bias[n])
//   omode 3: bf16 hi/lo -> natural [B,H,S,DH]; m=token, n=feature (bias[n])
//   omode 4: bf16 hi/lo -> V^T [B,H,DH,S];    m=feature, n=token  (bias[m])
// ---------------------------------------------------------------------------
#define BK    32
#define SST   40                     // smem row stride (bf16)
#define SMATE (128 * SST)
#define STAGE (2 * SMATE)
#define NCHUNK (KSPLIT / BK)         // 96

__global__ __launch_bounds__(256, 1) void mma_gemm_kernel(
    const unsigned short* __restrict__ Abuf, const unsigned short* __restrict__ Wbuf,
    const float* __restrict__ bias, float* __restrict__ out,
    unsigned short* __restrict__ ohi, unsigned short* __restrict__ olo,
    int omode, float scale)
{
    __shared__ __align__(16) unsigned short sbuf[2 * STAGE];  // 40960 B

    const int tid  = threadIdx.x;
    const int wid  = tid >> 5, lane = tid & 31;
    const int wm   = wid >> 2, wn = wid & 3;
    const int m0   = blockIdx.y * 128, n0 = blockIdx.x * 128;

    const uint32_t sb = smem_u32(sbuf);

    float acc[4][4][4];
    #pragma unroll
    for (int i = 0; i < 4; i++)
        #pragma unroll
        for (int j = 0; j < 4; j++)
            #pragma unroll
            for (int e = 0; e < 4; e++) acc[i][j][e] = 0.f;

    const int lrow0 = tid >> 2, lseg = (tid & 3) * 8;

    // preload stage 0
    {
        const unsigned short* Ap = Abuf + (size_t)(m0 + lrow0) * KSPLIT + lseg;
        const unsigned short* Bp = Wbuf + (size_t)(n0 + lrow0) * KSPLIT + lseg;
        *reinterpret_cast<uint4*>(sbuf + lrow0 * SST + lseg) =
            *reinterpret_cast<const uint4*>(Ap);
        *reinterpret_cast<uint4*>(sbuf + (lrow0 + 64) * SST + lseg) =
            *reinterpret_cast<const uint4*>(Ap + (size_t)64 * KSPLIT);
        *reinterpret_cast<uint4*>(sbuf + SMATE + lrow0 * SST + lseg) =
            *reinterpret_cast<const uint4*>(Bp);
        *reinterpret_cast<uint4*>(sbuf + SMATE + (lrow0 + 64) * SST + lseg) =
            *reinterpret_cast<const uint4*>(Bp + (size_t)64 * KSPLIT);
    }
    __syncthreads();

    const int a_row  = wm * 64 + (lane & 15);
    const int a_colh = (lane >> 4) * 8;
    const int b_row  = wn * 32 + (lane & 7);
    const int b_colh = ((lane >> 3) & 1) * 8;

    for (int c = 0; c < NCHUNK; c++) {
        const int st = c & 1;
        const uint32_t sa  = sb + (uint32_t)(st * STAGE) * 2;
        const uint32_t sbm = sa + (uint32_t)SMATE * 2;

        uint4 pa0, pa1, pb0, pb1;
        if (c + 1 < NCHUNK) {
            const int k0 = (c + 1) * BK;
            const unsigned short* Ap = Abuf + (size_t)(m0 + lrow0) * KSPLIT + k0 + lseg;
            const unsigned short* Bp = Wbuf + (size_t)(n0 + lrow0) * KSPLIT + k0 + lseg;
            pa0 = *reinterpret_cast<const uint4*>(Ap);
            pa1 = *reinterpret_cast<const uint4*>(Ap + (size_t)64 * KSPLIT);
            pb0 = *reinterpret_cast<const uint4*>(Bp);
            pb1 = *reinterpret_cast<const uint4*>(Bp + (size_t)64 * KSPLIT);
        }

        #pragma unroll
        for (int ks = 0; ks < 2; ks++) {
            uint32_t a[4][4], b[4][2];
            #pragma unroll
            for (int mt = 0; mt < 4; mt++) {
                const uint32_t addr = sa +
                    ((a_row + mt * 16) * SST + ks * 16 + a_colh) * 2;
                ldsm_x4(a[mt][0], a[mt][1], a[mt][2], a[mt][3], addr);
            }
            #pragma unroll
            for (int nt = 0; nt < 4; nt++) {
                const uint32_t addr = sbm +
                    ((b_row + nt * 8) * SST + ks * 16 + b_colh) * 2;
                ldsm_x2(b[nt][0], b[nt][1], addr);
            }
            #pragma unroll
            for (int mt = 0; mt < 4; mt++)
                #pragma unroll
                for (int nt = 0; nt < 4; nt++)
                    mma16816(acc[mt][nt], a[mt], b[nt]);
        }

        if (c + 1 < NCHUNK) {
            unsigned short* d = sbuf + (st ^ 1) * STAGE;
            *reinterpret_cast<uint4*>(d + lrow0 * SST + lseg) = pa0;
            *reinterpret_cast<uint4*>(d + (lrow0 + 64) * SST + lseg) = pa1;
            *reinterpret_cast<uint4*>(d + SMATE + lrow0 * SST + lseg) = pb0;
            *reinterpret_cast<uint4*>(d + SMATE + (lrow0 + 64) * SST + lseg) = pb1;
        }
        __syncthreads();
    }

    const int gr = lane >> 2, gc = (lane & 3) * 2;
    #pragma unroll
    for (int mt = 0; mt < 4; mt++) {
        #pragma unroll
        for (int nt = 0; nt < 4; nt++) {
            const int n = n0 + wn * 32 + nt * 8 + gc;
            #pragma unroll
            for (int half = 0; half < 2; half++) {
                const int m = m0 + wm * 64 + mt * 16 + gr + half * 8;
                float bb0, bb1;
                if (omode == 4) { bb0 = bb1 = bias[m]; }
                else           { bb0 = bias[n]; bb1 = bias[n + 1]; }
                const float v0 = (acc[mt][nt][half * 2 + 0] + bb0) * scale;
                const float v1 = (acc[mt][nt][half * 2 + 1] + bb1) * scale;
                if (omode == 0) {
                    *reinterpret_cast<float2*>(out + (size_t)m * D_ + n) =
                        make_float2(v0, v1);
                } else if (omode == 3) {
                    const int bb = m >> 11, s = m & (S_ - 1);
                    const int hh = n >> 6, dh = n & 63;
                    const size_t ad = (((size_t)bb * H_ + hh) * S_ + s) * DH_ + dh;
                    const ushort2 sh = make_ushort2(f2bf(v0), f2bf(v1));
                    const ushort2 sl = make_ushort2(f2bf(v0 - bf2f(sh.x)),
                                                    f2bf(v1 - bf2f(sh.y)));
                    *reinterpret_cast<ushort2*>(ohi + ad) = sh;
                    *reinterpret_cast<ushort2*>(olo + ad) = sl;
                } else {  // omode 4: V^T
                    const int hh = m >> 6, dh = m & 63;
                    const int bb = n >> 11, s = n & (S_ - 1);
                    const size_t ad = (((size_t)bb * H_ + hh) * DH_ + dh) * S_ + s;
                    const ushort2 sh = make_ushort2(f2bf(v0), f2bf(v1));
                    const ushort2 sl = make_ushort2(f2bf(v0 - bf2f(sh.x)),
                                                    f2bf(v1 - bf2f(sh.y)));
                    *reinterpret_cast<ushort2*>(ohi + ad) = sh;
                    *reinterpret_cast<ushort2*>(olo + ad) = sl;
                }
            }
        }
    }
}

// ---------------------------------------------------------------------------
// Tensorized flash attention. Block = 128 q rows x one (b,h). 8 warps, each
// warp owns 16 q rows (full 64-key tile width). bf16 split QK (3 mma) and
// PV (3 mma, P-frags built from score C-frags). cp.async double buffering.
// ---------------------------------------------------------------------------
#define FST   72                     // smem row stride (ushort), conflict-free
#define FARRB (64 * FST * 2)         // bytes per 64-row array = 9216
#define FSTGB (4 * FARRB)            // per stage = 36864 B
#define FSMEM (2 * FSTGB)            // 73728 B

__global__ __launch_bounds__(256, 1) void flash_mma_kernel()
{
    extern __shared__ __align__(16) unsigned char fsm[];
    const int tid = threadIdx.x, w = tid >> 5, lane = tid & 31;
    const int q0 = blockIdx.x * 128;
    const int h  = blockIdx.y, b = blockIdx.z;
    const size_t hb = ((size_t)b * H_ + h) * (size_t)(S_ * DH_);
    const uint32_t sb = smem_u32(fsm);

    // ---- Q load (hi at 0, lo at FSTGB) and fragment extraction
    #pragma unroll
    for (int i = 0; i < 4; i++) {
        const int f = tid + i * 256;
        const int r = f >> 3, sg = f & 7;
        const size_t gq = hb + (size_t)(q0 + r) * DH_ + sg * 8;
        *reinterpret_cast<uint4*>(fsm + (r * FST + sg * 8) * 2) =
            *reinterpret_cast<const uint4*>(g_qhi + gq);
        *reinterpret_cast<uint4*>(fsm + FSTGB + (r * FST + sg * 8) * 2) =
            *reinterpret_cast<const uint4*>(g_qlo + gq);
    }
    __syncthreads();
    uint32_t qh[4][4], ql[4][4];
    {
        const int ar = w * 16 + (lane & 15);
        const int ac = (lane >> 4) * 8;
        #pragma unroll
        for (int kc = 0; kc < 4; kc++) {
            const uint32_t ad = sb + (ar * FST + kc * 16 + ac) * 2;
            ldsm_x4(qh[kc][0], qh[kc][1], qh[kc][2], qh[kc][3], ad);
            ldsm_x4(ql[kc][0], ql[kc][1], ql[kc][2], ql[kc][3], ad + FSTGB);
        }
    }
    __syncthreads();

    const int gr = lane >> 2, gc = (lane & 3) * 2;
    const int brow  = (lane & 7) + ((lane >> 4) & 1) * 8;
    const int bcolh = ((lane >> 3) & 1) * 8;

    float o_[8][4];
    #pragma unroll
    for (int nt = 0; nt < 8; nt++)
        #pragma unroll
        for (int e = 0; e < 4; e++) o_[nt][e] = 0.f;
    float mI[2] = {-1e30f, -1e30f}, lI[2] = {0.f, 0.f};

    // KV stage issue (cp.async, 8 x 16B per thread)
    auto issue_kv = [&](int kt, int st) {
        const uint32_t s0 = sb + st * FSTGB;
        const int k0 = kt * 64;
        #pragma unroll
        for (int i = 0; i < 2; i++) {
            const int f = tid + i * 256;
            const int r = f >> 3, sg = f & 7;
            const uint32_t so = (r * FST + sg * 8) * 2;
            const size_t kg = hb + (size_t)(k0 + r) * DH_ + sg * 8;
            cpa16(s0 + so,             g_khi + kg);
            cpa16(s0 + FARRB + so,     g_klo + kg);
            const size_t vg = hb + (size_t)r * S_ + k0 + sg * 8;
            cpa16(s0 + 2 * FARRB + so, g_vhiT + vg);
            cpa16(s0 + 3 * FARRB + so, g_vloT + vg);
        }
    };

    issue_kv(0, 0);
    asm volatile("cp.async.commit_group;" ::: "memory");

    for (int kt = 0; kt < S_ / 64; kt++) {
        const int st = kt & 1;
        if (kt + 1 < S_ / 64) {
            issue_kv(kt + 1, st ^ 1);
            asm volatile("cp.async.commit_group;" ::: "memory");
            asm volatile("cp.async.wait_group 1;" ::: "memory");
        } else {
            asm volatile("cp.async.wait_group 0;" ::: "memory");
        }
        __syncthreads();

        const uint32_t sk = sb + st * FSTGB;

        // ---- QK^T: 3-term split
        float s_[8][4];
        #pragma unroll
        for (int nt = 0; nt < 8; nt++)
            #pragma unroll
            for (int e = 0; e < 4; e++) s_[nt][e] = 0.f;

        #pragma unroll
        for (int kc = 0; kc < 4; kc++) {
            #pragma unroll
            for (int ntp = 0; ntp < 4; ntp++) {
                const uint32_t ad = sk + ((ntp * 16 + brow) * FST + kc * 16 + bcolh) * 2;
                uint32_t r0, r1, r2, r3;
                ldsm_x4(r0, r1, r2, r3, ad);
                { uint32_t b0[2] = {r0, r1}, b1[2] = {r2, r3};
                  mma16816(s_[2 * ntp],     qh[kc], b0);
                  mma16816(s_[2 * ntp + 1], qh[kc], b1);
                  mma16816(s_[2 * ntp],     ql[kc], b0);
                  mma16816(s_[2 * ntp + 1], ql[kc], b1); }
                ldsm_x4(r0, r1, r2, r3, ad + FARRB);
                { uint32_t b0[2] = {r0, r1}, b1[2] = {r2, r3};
                  mma16816(s_[2 * ntp],     qh[kc], b0);
                  mma16816(s_[2 * ntp + 1], qh[kc], b1); }
            }
        }

        // ---- mask
        const int k0 = kt * 64;
        #pragma unroll
        for (int rh = 0; rh < 2; rh++) {
            const size_t mr = ((size_t)b * S_ + (q0 + w * 16 + gr + rh * 8)) * S_ + k0 + gc;
            #pragma unroll
            for (int nt = 0; nt < 8; nt++) {
                const uchar2 mv = *reinterpret_cast<const uchar2*>(g_mask + mr + nt * 8);
                if (mv.x) s_[nt][rh * 2 + 0] = -1e30f;
                if (mv.y) s_[nt][rh * 2 + 1] = -1e30f;
            }
        }

        // ---- online softmax (row = 4 lanes of a quad)
        float alpha[2];
        #pragma unroll
        for (int rh = 0; rh < 2; rh++) {
            float rmax = -1e30f;
            #pragma unroll
            for (int nt = 0; nt < 8; nt++)
                rmax = fmaxf(rmax, fmaxf(s_[nt][rh * 2], s_[nt][rh * 2 + 1]));
            rmax = fmaxf(rmax, __shfl_xor_sync(0xffffffffu, rmax, 1));
            rmax = fmaxf(rmax, __shfl_xor_sync(0xffffffffu, rmax, 2));
            const float mn = fmaxf(mI[rh], rmax);
            alpha[rh] = exp_fast(mI[rh] - mn);
            mI[rh] = mn;
            float rs = 0.f;
            #pragma unroll
            for (int nt = 0; nt < 8; nt++) {
                const float e0 = exp_fast(s_[nt][rh * 2] - mn);
                const float e1 = exp_fast(s_[nt][rh * 2 + 1] - mn);
                s_[nt][rh * 2] = e0; s_[nt][rh * 2 + 1] = e1;
                rs += e0 + e1;
            }
            rs += __shfl_xor_sync(0xffffffffu, rs, 1);
            rs += __shfl_xor_sync(0xffffffffu, rs, 2);
            lI[rh] = lI[rh] * alpha[rh] + rs;
        }
        #pragma unroll
        for (int nt = 0; nt < 8; nt++)
            #pragma unroll
            for (int e = 0; e < 4; e++) o_[nt][e] *= alpha[e >> 1];

        // ---- P @ V: 3-term split (P-frags from score C-frags)
        const uint32_t sv = sk + 2 * FARRB;
        #pragma unroll
        for (int kc2 = 0; kc2 < 4; kc2++) {
            uint32_t ah[4], al[4];
            #pragma unroll
            for (int jj = 0; jj < 2; jj++) {
                const float* sp = s_[2 * kc2 + jj];
                const unsigned short h0 = f2bf(sp[0]), h1 = f2bf(sp[1]);
                const unsigned short h2 = f2bf(sp[2]), h3 = f2bf(sp[3]);
                ah[jj * 2 + 0] = (uint32_t)h0 | ((uint32_t)h1 << 16);
                ah[jj * 2 + 1] = (uint32_t)h2 | ((uint32_t)h3 << 16);
                al[jj * 2 + 0] = packbf2(sp[0] - bf2f(h0), sp[1] - bf2f(h1));
                al[jj * 2 + 1] = packbf2(sp[2] - bf2f(h2), sp[3] - bf2f(h3));
            }
            #pragma unroll
            for (int ntp = 0; ntp < 4; ntp++) {
                const uint32_t ad = sv + ((ntp * 16 + brow) * FST + kc2 * 16 + bcolh) * 2;
                uint32_t r0, r1, r2, r3;
                ldsm_x4(r0, r1, r2, r3, ad);
                { uint32_t b0[2] = {r0, r1}, b1[2] = {r2, r3};
                  mma16816(o_[2 * ntp],     ah, b0);
                  mma16816(o_[2 * ntp + 1], ah, b1);
                  mma16816(o_[2 * ntp],     al, b0);
                  mma16816(o_[2 * ntp + 1], al, b1); }
                ldsm_x4(r0, r1, r2, r3, ad + FARRB);
                { uint32_t b0[2] = {r0, r1}, b1[2] = {r2, r3};
                  mma16816(o_[2 * ntp],     ah, b0);
                  mma16816(o_[2 * ntp + 1], ah, b1); }
            }
        }
        __syncthreads();
    }

    // ---- finalize: ctx natural [B,H,S,DH]
    const float inv0 = 1.f / lI[0], inv1 = 1.f / lI[1];
    #pragma unroll
    for (int nt = 0; nt < 8; nt++) {
        const int d = nt * 8 + gc;
        const int qA = q0 + w * 16 + gr;
        *reinterpret_cast<float2*>(g_ctx + hb + (size_t)qA * DH_ + d) =
            make_float2(o_[nt][0] * inv0, o_[nt][1] * inv0);
        *reinterpret_cast<float2*>(g_ctx + hb + (size_t)(qA + 8) * DH_ + d) =
            make_float2(o_[nt][2] * inv1, o_[nt][3] * inv1);
    }
}

// ---------------------------------------------------------------------------
extern "C" void kernel_launch(void* const* d_in, const int* in_sizes, int n_in,
                              void* d_out, int out_size)
{
    const float* key   = (const float*)d_in[0];
    const float* value = (const float*)d_in[1];
    const float* query = (const float*)d_in[2];
    const void*  mask  = d_in[3];
    const float* Wq = (const float*)d_in[4];
    const float* bq = (const float*)d_in[5];
    const float* Wk = (const float*)d_in[6];
    const float* bk = (const float*)d_in[7];
    const float* Wv = (const float*)d_in[8];
    const float* bv = (const float*)d_in[9];
    const float* Wo = (const float*)d_in[10];
    const float* bo = (const float*)d_in[11];
    float* out = (float*)d_out;

    void *pctx, *pa, *pw, *pqh, *pql, *pkh, *pkl, *pvh, *pvl;
    cudaGetSymbolAddress(&pctx, g_ctx);
    cudaGetSymbolAddress(&pa,   g_abuf);
    cudaGetSymbolAddress(&pw,   g_wbuf);
    cudaGetSymbolAddress(&pqh,  g_qhi);
    cudaGetSymbolAddress(&pql,  g_qlo);
    cudaGetSymbolAddress(&pkh,  g_khi);
    cudaGetSymbolAddress(&pkl,  g_klo);
    cudaGetSymbolAddress(&pvh,  g_vhiT);
    cudaGetSymbolAddress(&pvl,  g_vloT);
    const unsigned short* abuf = (const unsigned short*)pa;
    const unsigned short* wbuf = (const unsigned short*)pw;

    // mask normalization (dtype-agnostic)
    detect_mask_kernel<<<1, 256>>>((const uint32_t*)mask);
    convert_mask_kernel<<<(MASK_N / 4 + 255) / 256, 256>>>(mask);

    const dim3 gg(D_ / 128, MTOT / 128);    // (8, 32): m = tokens
    const dim3 gv(MTOT / 128, D_ / 128);    // (32, 8): m = features (V^T)
    const int ga = (MTOT * D_ / 4) / 256;
    const int gw = (D_ * D_ / 4) / 256;

    // Q -> bf16 hi/lo natural, pre-scaled by 1/sqrt(DH)
    split_W_kernel<<<gw, 256>>>(Wq);
    split_A_kernel<<<ga, 256>>>(query, 0);
    mma_gemm_kernel<<<gg, 256>>>(abuf, wbuf, bq, nullptr,
                                 (unsigned short*)pqh, (unsigned short*)pql, 3, 0.125f);
    // K -> bf16 hi/lo natural
    split_W_kernel<<<gw, 256>>>(Wk);
    split_A_kernel<<<ga, 256>>>(key, 0);
    mma_gemm_kernel<<<gg, 256>>>(abuf, wbuf, bk, nullptr,
                                 (unsigned short*)pkh, (unsigned short*)pkl, 3, 1.f);
    // V -> bf16 hi/lo transposed [B,H,DH,S] via swapped operands (V^T = Wv X^T)
    split_W_kernel<<<gw, 256>>>(Wv);
    split_A_kernel<<<ga, 256>>>(value, 0);
    mma_gemm_kernel<<<gv, 256>>>(wbuf, abuf, bv, nullptr,
                                 (unsigned short*)pvh, (unsigned short*)pvl, 4, 1.f);

    // attention (tensorized)
    cudaFuncSetAttribute(flash_mma_kernel,
                         cudaFuncAttributeMaxDynamicSharedMemorySize, FSMEM);
    flash_mma_kernel<<<dim3(S_ / 128, H_, B_), 256, FSMEM>>>();

    // output projection
    split_W_kernel<<<gw, 256>>>(Wo);
    split_A_kernel<<<ga, 256>>>((const float*)pctx, 1);
    mma_gemm_kernel<<<gg, 256>>>(abuf, wbuf, bo, out, nullptr, nullptr, 0, 1.f);
}